// round 10
// baseline (speedup 1.0000x reference)
#include <cuda_runtime.h>
#include <cuda_fp16.h>
#include <cstdint>
#include <cstddef>

// Shapes: x[32,64,25,1024], W[25,192,64], A[3,25,25], out[32,64,25,1024]
// FUSED kernel: per CTA (j-tile 64, c-group 16):
//   loop w: stage1 HMMA  D[48,64] = W[w, 3c0..3c0+48, :] @ X_w[64, j-tile]
//           -> sY[cloc*75 + k*25 + w][jloc]  (fp16, smem-resident)
//   stage2 HMMA: out[c, v, j] = sum_r A[v,r] * sY[cloc*75+r][jloc]
// Y never touches DRAM.

#define NB 32
#define CC 64
#define VV 25
#define TT 1024
#define KK 3
#define OO 192
#define NT 32768
#define CG 16             /* c per CTA */
#define JT 64             /* j per CTA */

#define YST 72            /* sY row stride (halves) */
#define XST 72
#define WST 72
#define AST 88

#define OFF_Y   0
#define SZ_Y    (CG * 75 * YST * 2)       /* 172800 */
#define OFF_X   SZ_Y
#define SZ_XB   (64 * XST * 2)            /* 9216, x2 buffers */
#define OFF_W   (OFF_X + 2 * SZ_XB)       /* 191232 */
#define SZ_WB   (48 * WST * 2)            /* 6912, x2 buffers */
#define OFF_AH  (OFF_W + 2 * SZ_WB)       /* 205056 */
#define OFF_AL  (OFF_AH + 32 * AST * 2)   /* 210688 */
#define SMEM_TOTAL (OFF_AL + 32 * AST * 2) /* 216320 */

// ---------------------------------------------------------------------------
// helpers
// ---------------------------------------------------------------------------
__device__ __forceinline__ uint32_t smem_u32(const void* p) {
    uint32_t a;
    asm("{ .reg .u64 t; cvta.to.shared.u64 t, %1; cvt.u32.u64 %0, t; }"
        : "=r"(a) : "l"(p));
    return a;
}
__device__ __forceinline__ void ldm_x4(uint32_t a[4], uint32_t addr) {
    asm volatile("ldmatrix.sync.aligned.m8n8.x4.shared.b16 {%0,%1,%2,%3}, [%4];"
        : "=r"(a[0]), "=r"(a[1]), "=r"(a[2]), "=r"(a[3]) : "r"(addr));
}
// x4 trans: lanes 0-15 rows (k), lanes 16-31 same rows col+8.
// Returns frags for n8 at col+0 in {r0,r1}, col+8 in {r2,r3}.
__device__ __forceinline__ void ldm_x4t(uint32_t a[4], uint32_t addr) {
    asm volatile("ldmatrix.sync.aligned.m8n8.x4.trans.shared.b16 {%0,%1,%2,%3}, [%4];"
        : "=r"(a[0]), "=r"(a[1]), "=r"(a[2]), "=r"(a[3]) : "r"(addr));
}
__device__ __forceinline__ void mma_f16(float c[4], const uint32_t a[4],
                                        const uint32_t b[2]) {
    asm volatile("mma.sync.aligned.m16n8k16.row.col.f32.f16.f16.f32 "
        "{%0,%1,%2,%3}, {%4,%5,%6,%7}, {%8,%9}, {%0,%1,%2,%3};"
        : "+f"(c[0]), "+f"(c[1]), "+f"(c[2]), "+f"(c[3])
        : "r"(a[0]), "r"(a[1]), "r"(a[2]), "r"(a[3]), "r"(b[0]), "r"(b[1]));
}

// ---------------------------------------------------------------------------
__global__ __launch_bounds__(512, 1) void fused_gc(
    const float* __restrict__ x, const float* __restrict__ Wg,
    const float* __restrict__ Ag, float* __restrict__ out)
{
    extern __shared__ char sm[];
    const uint32_t sb = smem_u32(sm);

    const int tid  = threadIdx.x;
    const int wid  = tid >> 5, lane = tid & 31;
    const int c0   = blockIdx.x * CG;     // c-group fastest -> x L2 reuse
    const int j0   = blockIdx.y * JT;
    const int n    = j0 >> 10;            // JT=64 never crosses n
    const int t0   = j0 & 1023;

    // ---- build graph A hi/lo fp16 (zero-padded v>=25, r>=75) ----
    {
        __half* sAh = (__half*)(sm + OFF_AH);
        __half* sAl = (__half*)(sm + OFF_AL);
        for (int i = tid; i < 80 * 32; i += 512) {
            int r = i >> 5, v = i & 31;
            float a = (r < 75 && v < 25) ? Ag[r * 25 + v] : 0.0f;
            __half h = __float2half_rn(a);
            sAh[v * AST + r] = h;
            sAl[v * AST + r] = __float2half_rn(a - __half2float(h));
        }
    }

    const float* xb = x + (size_t)n * CC * VV * TT + t0;   // + c'*V*T + w*T
    const float* wb = Wg + (size_t)(3 * c0) * 64;          // + w*OO*64 + o*64

    // ---- prologue: load w=0 into buffer 0 ----
    #pragma unroll
    for (int s = 0; s < 4; ++s) {
        int idx = tid + s * 512;
        int r = idx >> 5, cp = idx & 31;
        float2 v = *(const float2*)(xb + (size_t)r * (VV * TT) + cp * 2);
        *(__half2*)(sm + OFF_X + (r * XST + cp * 2) * 2) =
            __floats2half2_rn(v.x, v.y);
    }
    #pragma unroll
    for (int s = 0; s < 3; ++s) {
        int idx = tid + s * 512;
        int o = idx >> 5, cp = idx & 31;
        float2 v = *(const float2*)(wb + (size_t)o * 64 + cp * 2);
        *(__half2*)(sm + OFF_W + (o * WST + cp * 2) * 2) =
            __floats2half2_rn(v.x, v.y);
    }
    __syncthreads();

    const int arow = lane & 15, acolb = (lane >> 4) * 8;
    const int brow = lane & 15, bcol = (lane >> 4) * 8;
    const int r4 = lane >> 2, q2 = (lane & 3) * 2;

    // ---- main loop over w: stage1 into sY ----
    for (int w = 0; w < 25; ++w) {
        const int b = w & 1;

        // prefetch w+1 into registers (overlaps with MMA below)
        float2 xr[4], wr[3];
        if (w < 24) {
            const float* xw = xb + (size_t)(w + 1) * TT;
            #pragma unroll
            for (int s = 0; s < 4; ++s) {
                int idx = tid + s * 512;
                int r = idx >> 5, cp = idx & 31;
                xr[s] = *(const float2*)(xw + (size_t)r * (VV * TT) + cp * 2);
            }
            const float* ww = wb + (size_t)(w + 1) * OO * 64;
            #pragma unroll
            for (int s = 0; s < 3; ++s) {
                int idx = tid + s * 512;
                int o = idx >> 5, cp = idx & 31;
                wr[s] = *(const float2*)(ww + (size_t)o * 64 + cp * 2);
            }
        }

        // stage1 MMA: warps 0..11, warp = (mi, jh): D[m16, j16]
        if (wid < 12) {
            const int mi = wid >> 2, jh = wid & 3;
            const int m0 = mi * 16, nn0 = jh * 16;
            const uint32_t WB = sb + OFF_W + b * SZ_WB;
            const uint32_t XB = sb + OFF_X + b * SZ_XB;

            float acc[2][4] = {};
            #pragma unroll
            for (int ks = 0; ks < 4; ++ks) {
                uint32_t Af[4], Bf[4];
                ldm_x4(Af, WB + (uint32_t)(((m0 + arow) * WST
                                            + ks * 16 + acolb) * 2));
                ldm_x4t(Bf, XB + (uint32_t)(((ks * 16 + brow) * XST
                                             + nn0 + bcol) * 2));
                mma_f16(acc[0], Af, Bf);       // n8 at nn0
                mma_f16(acc[1], Af, Bf + 2);   // n8 at nn0+8
            }
            // store D frags -> sY rows (oloc/3)*75 + (oloc%3)*25 + w
            #pragma unroll
            for (int t = 0; t < 2; ++t) {
                int col = nn0 + t * 8 + q2;
                int ol0 = m0 + r4, ol1 = ol0 + 8;
                int y0 = (ol0 / 3) * 75 + (ol0 % 3) * 25 + w;
                int y1 = (ol1 / 3) * 75 + (ol1 % 3) * 25 + w;
                *(__half2*)(sm + OFF_Y + (y0 * YST + col) * 2) =
                    __floats2half2_rn(acc[t][0], acc[t][1]);
                *(__half2*)(sm + OFF_Y + (y1 * YST + col) * 2) =
                    __floats2half2_rn(acc[t][2], acc[t][3]);
            }
        }

        // store prefetched regs into the other buffer
        if (w < 24) {
            char* xd = sm + OFF_X + (b ^ 1) * SZ_XB;
            char* wd = sm + OFF_W + (b ^ 1) * SZ_WB;
            #pragma unroll
            for (int s = 0; s < 4; ++s) {
                int idx = tid + s * 512;
                int r = idx >> 5, cp = idx & 31;
                *(__half2*)(xd + (r * XST + cp * 2) * 2) =
                    __floats2half2_rn(xr[s].x, xr[s].y);
            }
            #pragma unroll
            for (int s = 0; s < 3; ++s) {
                int idx = tid + s * 512;
                int o = idx >> 5, cp = idx & 31;
                *(__half2*)(wd + (o * WST + cp * 2) * 2) =
                    __floats2half2_rn(wr[s].x, wr[s].y);
            }
        }
        __syncthreads();
    }

    // ---- stage2: each warp handles one c; D[v=32, j=64] = A[32,80] @ Y[80,64]
    {
        const int cloc = wid;
        const int c = c0 + cloc;
        const uint32_t AHs = sb + OFF_AH, ALs = sb + OFF_AL;
        const uint32_t Yb = sb + OFF_Y + (uint32_t)(cloc * 75 * YST * 2);

        float acc2[2][8][4] = {};
        #pragma unroll
        for (int ks = 0; ks < 5; ++ks) {
            // rows past 75 within a c-block read the next block / X buffers:
            // finite fp16 garbage nullified by zero-padded A cols 75..79.
            uint32_t ah0[4], ah1[4], al0[4], al1[4];
            uint32_t ao0 = (uint32_t)(((arow) * AST + ks * 16 + acolb) * 2);
            uint32_t ao1 = (uint32_t)(((16 + arow) * AST + ks * 16 + acolb) * 2);
            ldm_x4(ah0, AHs + ao0);
            ldm_x4(ah1, AHs + ao1);
            ldm_x4(al0, ALs + ao0);
            ldm_x4(al1, ALs + ao1);
            #pragma unroll
            for (int t = 0; t < 4; ++t) {
                uint32_t Bf[4];
                ldm_x4t(Bf, Yb + (uint32_t)(((ks * 16 + brow) * YST
                                             + t * 16 + bcol) * 2));
                mma_f16(acc2[0][2 * t],     ah0, Bf);
                mma_f16(acc2[0][2 * t],     al0, Bf);
                mma_f16(acc2[0][2 * t + 1], ah0, Bf + 2);
                mma_f16(acc2[0][2 * t + 1], al0, Bf + 2);
                mma_f16(acc2[1][2 * t],     ah1, Bf);
                mma_f16(acc2[1][2 * t],     al1, Bf);
                mma_f16(acc2[1][2 * t + 1], ah1, Bf + 2);
                mma_f16(acc2[1][2 * t + 1], al1, Bf + 2);
            }
        }

        float* ob = out + (((size_t)n * CC + c) * VV) * TT + t0;
        #pragma unroll
        for (int m = 0; m < 2; ++m) {
            int v0 = m * 16 + r4, v1 = v0 + 8;
            #pragma unroll
            for (int t = 0; t < 8; ++t) {
                int col = t * 8 + q2;
                if (v0 < VV)
                    *(float2*)(ob + (size_t)v0 * TT + col) =
                        make_float2(acc2[m][t][0], acc2[m][t][1]);
                if (v1 < VV)
                    *(float2*)(ob + (size_t)v1 * TT + col) =
                        make_float2(acc2[m][t][2], acc2[m][t][3]);
            }
        }
    }
}

// ---------------------------------------------------------------------------
extern "C" void kernel_launch(void* const* d_in, const int* in_sizes, int n_in,
                              void* d_out, int out_size)
{
    const float* x  = (const float*)d_in[0];
    const float* Wg = (const float*)d_in[1];
    const float* Ag = (const float*)d_in[2];
    float* out = (float*)d_out;

    cudaFuncSetAttribute(fused_gc,
                         cudaFuncAttributeMaxDynamicSharedMemorySize,
                         SMEM_TOTAL);

    dim3 g(CC / CG, NT / JT);          // (4, 512)
    fused_gc<<<g, 512, SMEM_TOTAL>>>(x, Wg, Ag, out);
}

// round 11
// speedup vs baseline: 1.0389x; 1.0389x over previous
#include <cuda_runtime.h>
#include <cuda_fp16.h>
#include <cstdint>
#include <cstddef>

// Shapes: x[32,64,25,1024], W[25,192,64], A[3,25,25], out[32,64,25,1024]
// FUSED v2: per CTA (c-group 8, j-tile 64):
//   loop w: stage1 HMMA D[32(24 real),64] = Wpad[w] @ X_w -> sY (smem fp16)
//   stage2 HMMA (single-pass fp16 A): out = A_pad[32,80] @ sY[80,64] per c.
// Y never touches DRAM. 2 CTAs/SM (103 KB smem) for latency hiding.

#define NB 32
#define CC 64
#define VV 25
#define TT 1024
#define KK 3
#define OO 192
#define NT 32768
#define CG 8              /* c per CTA */
#define JT 64             /* j per CTA */

#define YST 72            /* sY row stride (halves); 36 words = 4 mod 32 */
#define XST 72
#define WST 72
#define AST 88            /* 44 words = 12 mod 32: conflict-free x4 */

#define OFF_Y   0
#define SZ_Y    (CG * 75 * YST * 2)        /* 86400 */
#define OFF_X   SZ_Y
#define SZ_X    (64 * XST * 2)             /* 9216 */
#define OFF_W   (OFF_X + SZ_X)             /* 95616 */
#define SZ_W    (32 * WST * 2)             /* 4608 (rows 24-31 zero pad) */
#define OFF_A   (OFF_W + SZ_W)             /* 100224 */
#define SZ_A    (32 * AST * 2)             /* 5632 */
#define SMEM_TOTAL (OFF_A + SZ_A)          /* 105856 */

// ---------------------------------------------------------------------------
__device__ __forceinline__ uint32_t smem_u32(const void* p) {
    uint32_t a;
    asm("{ .reg .u64 t; cvta.to.shared.u64 t, %1; cvt.u32.u64 %0, t; }"
        : "=r"(a) : "l"(p));
    return a;
}
__device__ __forceinline__ void ldm_x4(uint32_t a[4], uint32_t addr) {
    asm volatile("ldmatrix.sync.aligned.m8n8.x4.shared.b16 {%0,%1,%2,%3}, [%4];"
        : "=r"(a[0]), "=r"(a[1]), "=r"(a[2]), "=r"(a[3]) : "r"(addr));
}
__device__ __forceinline__ void ldm_x4t(uint32_t a[4], uint32_t addr) {
    asm volatile("ldmatrix.sync.aligned.m8n8.x4.trans.shared.b16 {%0,%1,%2,%3}, [%4];"
        : "=r"(a[0]), "=r"(a[1]), "=r"(a[2]), "=r"(a[3]) : "r"(addr));
}
__device__ __forceinline__ void mma_f16(float c[4], const uint32_t a[4],
                                        const uint32_t b[2]) {
    asm volatile("mma.sync.aligned.m16n8k16.row.col.f32.f16.f16.f32 "
        "{%0,%1,%2,%3}, {%4,%5,%6,%7}, {%8,%9}, {%0,%1,%2,%3};"
        : "+f"(c[0]), "+f"(c[1]), "+f"(c[2]), "+f"(c[3])
        : "r"(a[0]), "r"(a[1]), "r"(a[2]), "r"(a[3]), "r"(b[0]), "r"(b[1]));
}

// ---------------------------------------------------------------------------
__global__ __launch_bounds__(256, 2) void fused_gc(
    const float* __restrict__ x, const float* __restrict__ Wg,
    const float* __restrict__ Ag, float* __restrict__ out)
{
    extern __shared__ char sm[];
    const uint32_t sb = smem_u32(sm);

    const int tid  = threadIdx.x;
    const int wid  = tid >> 5, lane = tid & 31;
    const int c0   = blockIdx.x * CG;     // c-group fastest -> x L2 reuse
    const int j0   = blockIdx.y * JT;
    const int n    = j0 >> 10;
    const int t0   = j0 & 1023;

    // ---- graph A fp16 (single pass), zero-padded v>=25, r>=75 ----
    {
        __half* sA = (__half*)(sm + OFF_A);
        for (int i = tid; i < 80 * 32; i += 256) {
            int r = i >> 5, v = i & 31;
            float a = (r < 75 && v < 25) ? Ag[r * 25 + v] : 0.0f;
            sA[v * AST + r] = __float2half_rn(a);
        }
    }
    // zero W pad rows 24..31 (never rewritten)
    for (int i = tid; i < 8 * WST; i += 256)
        ((__half*)(sm + OFF_W))[24 * WST + i] = __ushort_as_half(0);

    const float* xb = x + (size_t)n * CC * VV * TT + t0;    // + c'*V*T + w*T
    const float* wb = Wg + (size_t)(3 * c0) * 64;           // + w*OO*64 + o*64

    // ---- prologue: w = 0 into smem ----
    #pragma unroll
    for (int s = 0; s < 8; ++s) {
        int idx = tid + s * 256;
        int r = idx >> 5, cp = idx & 31;
        float2 v = *(const float2*)(xb + (size_t)r * (VV * TT) + cp * 2);
        *(__half2*)(sm + OFF_X + (r * XST + cp * 2) * 2) =
            __floats2half2_rn(v.x, v.y);
    }
    #pragma unroll
    for (int s = 0; s < 3; ++s) {
        int idx = tid + s * 256;
        int o = idx >> 5, cp = idx & 31;
        float2 v = *(const float2*)(wb + (size_t)o * 64 + cp * 2);
        *(__half2*)(sm + OFF_W + (o * WST + cp * 2) * 2) =
            __floats2half2_rn(v.x, v.y);
    }
    __syncthreads();

    const int arow = lane & 15, acolb = (lane >> 4) * 8;
    const int brow = lane & 15, bcol = (lane >> 4) * 8;
    const int r4 = lane >> 2, q2 = (lane & 3) * 2;

    // stage1 warp layout: 8 warps = 2 mi x 4 jh
    const int mi = wid >> 2, jh = wid & 3;
    const int m0 = mi * 16, nn0 = jh * 16;

    // ---- main loop over w ----
    for (int w = 0; w < 25; ++w) {
        // prefetch w+1 into registers (overlaps MMA)
        float2 xr[8], wr[3];
        if (w < 24) {
            const float* xw = xb + (size_t)(w + 1) * TT;
            #pragma unroll
            for (int s = 0; s < 8; ++s) {
                int idx = tid + s * 256;
                int r = idx >> 5, cp = idx & 31;
                xr[s] = *(const float2*)(xw + (size_t)r * (VV * TT) + cp * 2);
            }
            const float* ww = wb + (size_t)(w + 1) * OO * 64;
            #pragma unroll
            for (int s = 0; s < 3; ++s) {
                int idx = tid + s * 256;
                int o = idx >> 5, cp = idx & 31;
                wr[s] = *(const float2*)(ww + (size_t)o * 64 + cp * 2);
            }
        }

        // stage1 MMA: all 8 warps. D[m16, n16] per warp.
        {
            float acc[2][4] = {};
            #pragma unroll
            for (int ks = 0; ks < 4; ++ks) {
                uint32_t Af[4], Bf[4];
                ldm_x4(Af, sb + OFF_W + (uint32_t)(((m0 + arow) * WST
                                                   + ks * 16 + acolb) * 2));
                ldm_x4t(Bf, sb + OFF_X + (uint32_t)(((ks * 16 + brow) * XST
                                                     + nn0 + bcol) * 2));
                mma_f16(acc[0], Af, Bf);
                mma_f16(acc[1], Af, Bf + 2);
            }
            // store D -> sY rows (ol/3)*75 + (ol%3)*25 + w (ol < 24 only)
            #pragma unroll
            for (int t = 0; t < 2; ++t) {
                int col = nn0 + t * 8 + q2;
                int ol0 = m0 + r4;            // mi=0: 0-7, mi=1: 16-23 (<24 ok)
                int y0 = (ol0 / 3) * 75 + (ol0 % 3) * 25 + w;
                *(__half2*)(sm + OFF_Y + (y0 * YST + col) * 2) =
                    __floats2half2_rn(acc[t][0], acc[t][1]);
                int ol1 = ol0 + 8;            // mi=0: 8-15 ok; mi=1: 24-31 skip
                if (ol1 < 24) {
                    int y1 = (ol1 / 3) * 75 + (ol1 % 3) * 25 + w;
                    *(__half2*)(sm + OFF_Y + (y1 * YST + col) * 2) =
                        __floats2half2_rn(acc[t][2], acc[t][3]);
                }
            }
        }
        __syncthreads();                      // sX/sW reads complete

        if (w < 24) {
            #pragma unroll
            for (int s = 0; s < 8; ++s) {
                int idx = tid + s * 256;
                int r = idx >> 5, cp = idx & 31;
                *(__half2*)(sm + OFF_X + (r * XST + cp * 2) * 2) =
                    __floats2half2_rn(xr[s].x, xr[s].y);
            }
            #pragma unroll
            for (int s = 0; s < 3; ++s) {
                int idx = tid + s * 256;
                int o = idx >> 5, cp = idx & 31;
                *(__half2*)(sm + OFF_W + (o * WST + cp * 2) * 2) =
                    __floats2half2_rn(wr[s].x, wr[s].y);
            }
            __syncthreads();                  // new tiles visible
        }
    }

    // ---- stage2: warp wid owns c = c0+wid; D[32,64] = A[32,80] @ Y[80,64] ----
    {
        const int cloc = wid;
        const int c = c0 + cloc;
        const uint32_t As = sb + OFF_A;
        const uint32_t Yb = sb + OFF_Y + (uint32_t)(cloc * 75 * YST * 2);
        // rows 75..79 of the last c-block read into sX (finite fp16);
        // nullified by zero A cols 75..79.

        float acc2[2][8][4] = {};
        #pragma unroll
        for (int ks = 0; ks < 5; ++ks) {
            uint32_t a0[4], a1[4];
            ldm_x4(a0, As + (uint32_t)(((arow) * AST + ks * 16 + acolb) * 2));
            ldm_x4(a1, As + (uint32_t)(((16 + arow) * AST + ks * 16 + acolb) * 2));
            #pragma unroll
            for (int t = 0; t < 4; ++t) {
                uint32_t Bf[4];
                ldm_x4t(Bf, Yb + (uint32_t)(((ks * 16 + brow) * YST
                                             + t * 16 + bcol) * 2));
                mma_f16(acc2[0][2 * t],     a0, Bf);
                mma_f16(acc2[0][2 * t + 1], a0, Bf + 2);
                mma_f16(acc2[1][2 * t],     a1, Bf);
                mma_f16(acc2[1][2 * t + 1], a1, Bf + 2);
            }
        }

        float* ob = out + (((size_t)n * CC + c) * VV) * TT + t0;
        #pragma unroll
        for (int m = 0; m < 2; ++m) {
            int v0 = m * 16 + r4, v1 = v0 + 8;
            #pragma unroll
            for (int t = 0; t < 8; ++t) {
                int col = t * 8 + q2;
                if (v0 < VV)
                    *(float2*)(ob + (size_t)v0 * TT + col) =
                        make_float2(acc2[m][t][0], acc2[m][t][1]);
                if (v1 < VV)
                    *(float2*)(ob + (size_t)v1 * TT + col) =
                        make_float2(acc2[m][t][2], acc2[m][t][3]);
            }
        }
    }
}

// ---------------------------------------------------------------------------
extern "C" void kernel_launch(void* const* d_in, const int* in_sizes, int n_in,
                              void* d_out, int out_size)
{
    const float* x  = (const float*)d_in[0];
    const float* Wg = (const float*)d_in[1];
    const float* Ag = (const float*)d_in[2];
    float* out = (float*)d_out;

    cudaFuncSetAttribute(fused_gc,
                         cudaFuncAttributeMaxDynamicSharedMemorySize,
                         SMEM_TOTAL);

    dim3 g(CC / CG, NT / JT);          // (8, 512) = 4096 CTAs, 2/SM
    fused_gc<<<g, 256, SMEM_TOTAL>>>(x, Wg, Ag, out);
}

// round 12
// speedup vs baseline: 1.0432x; 1.0041x over previous
#include <cuda_runtime.h>
#include <cuda_fp16.h>
#include <cstdint>
#include <cstddef>

// Shapes: x[32,64,25,1024], W[25,192,64], A[3,25,25], out[32,64,25,1024]
// Single kernel, chunk-pipelined: blocks ordered [s1(ch0) s2(ch0) s1(ch1) ...].
// Stage 1 (HMMA fp16): Ybuf[c*75+k*25+w][jloc] = sum_c' W[w,c*3+k,c'] x[n,c',w,t]
// Stage 2 (HMMA fp16, A hi/lo): out[n,c,v,t] = sum_r A[v,r]*Ybuf[c*75+r][jloc]
// Y ping-pongs between two 19.7 MB chunk buffers (L2-resident).
// Cross-stage ordering via atomic counters; stage2(ch) waits s1(ch) complete;
// stage1(ch+2) waits s2(ch) complete before reusing the buffer.

#define NB 32
#define CC 64
#define VV 25
#define TT 1024
#define KK 3
#define OO 192
#define NT 32768
#define NTC 2048              /* j chunk */
#define NCHUNK (NT / NTC)     /* 16 */
#define S1B (25 * (NTC / 64)) /* 800 stage1 blocks per chunk */
#define S2B ((NTC / 128) * 8) /* 128 stage2 blocks per chunk */
#define BLK (S1B + S2B)       /* 928 */
#define WS1 72
#define JT  128
#define AST 88
#define YST 136
#define YROWS 4800            /* 64 c * 75 r */

__device__ unsigned short g_Yh[2 * (size_t)YROWS * NTC];  // 39.3 MB ping-pong
__device__ int g_s1[NCHUNK];
__device__ int g_s2[NCHUNK];

// ---------------------------------------------------------------------------
__device__ __forceinline__ uint32_t smem_u32(const void* p) {
    uint32_t a;
    asm("{ .reg .u64 t; cvta.to.shared.u64 t, %1; cvt.u32.u64 %0, t; }"
        : "=r"(a) : "l"(p));
    return a;
}
__device__ __forceinline__ void ldm_x4(uint32_t a[4], uint32_t addr) {
    asm volatile("ldmatrix.sync.aligned.m8n8.x4.shared.b16 {%0,%1,%2,%3}, [%4];"
        : "=r"(a[0]), "=r"(a[1]), "=r"(a[2]), "=r"(a[3]) : "r"(addr));
}
__device__ __forceinline__ void ldm_x2t(uint32_t b[2], uint32_t addr) {
    asm volatile("ldmatrix.sync.aligned.m8n8.x2.trans.shared.b16 {%0,%1}, [%2];"
        : "=r"(b[0]), "=r"(b[1]) : "r"(addr));
}
__device__ __forceinline__ void mma_f16(float c[4], const uint32_t a[4],
                                        const uint32_t b[2]) {
    asm volatile("mma.sync.aligned.m16n8k16.row.col.f32.f16.f16.f32 "
        "{%0,%1,%2,%3}, {%4,%5,%6,%7}, {%8,%9}, {%0,%1,%2,%3};"
        : "+f"(c[0]), "+f"(c[1]), "+f"(c[2]), "+f"(c[3])
        : "r"(a[0]), "r"(a[1]), "r"(a[2]), "r"(a[3]), "r"(b[0]), "r"(b[1]));
}

// ---------------------------------------------------------------------------
__global__ void reset_counters() {
    if (threadIdx.x < NCHUNK) {
        g_s1[threadIdx.x] = 0;
        g_s2[threadIdx.x] = 0;
    }
}

// ---------------------------------------------------------------------------
__global__ __launch_bounds__(256) void fused_pipe(
    const float* __restrict__ x, const float* __restrict__ Wg,
    const float* __restrict__ Ag, float* __restrict__ out)
{
    extern __shared__ char sm[];
    const uint32_t sb = smem_u32(sm);
    const int tid = threadIdx.x;
    const int bid = blockIdx.x;
    const int ch  = bid / BLK;
    const int lb  = bid - ch * BLK;
    const int jbase = ch * NTC;
    unsigned short* ybuf = g_Yh + (size_t)(ch & 1) * ((size_t)YROWS * NTC);

    if (lb < S1B) {
        // ================= STAGE 1 =================
        // Wait for buffer release by stage2(ch-2).
        if (ch >= 2) {
            if (tid == 0)
                while (((volatile int*)g_s2)[ch - 2] < S2B) __nanosleep(64);
            __syncthreads();
        }

        __half* sW = (__half*)sm;                       // 192 x 72
        __half* sX = (__half*)(sm + OO * WS1 * 2);      // 64 x 72
        const uint32_t WHs = sb;
        const uint32_t XHs = sb + OO * WS1 * 2;

        const int w    = lb >> 5;           // 0..24
        const int jloc = (lb & 31) * 64;    // 0..2047
        const int jg   = jbase + jloc;
        const int n    = jg >> 10;
        const int t0   = jg & 1023;

        {
            const float* wg = Wg + (size_t)w * OO * 64;
            #pragma unroll
            for (int i = 0; i < 24; ++i) {
                int idx = tid + i * 256;
                int o = idx >> 5, cp = idx & 31;
                float2 wv = *(const float2*)(wg + (size_t)o * 64 + cp * 2);
                *(__half2*)&sW[o * WS1 + cp * 2] = __floats2half2_rn(wv.x, wv.y);
            }
        }
        {
            const float* xb = x + (size_t)n * CC * VV * TT + (size_t)w * TT + t0;
            #pragma unroll
            for (int i = 0; i < 8; ++i) {
                int idx = tid + i * 256;
                int r = idx >> 5, cp = idx & 31;
                float2 xv = *(const float2*)(xb + (size_t)r * (VV * TT) + cp * 2);
                *(__half2*)&sX[r * WS1 + cp * 2] = __floats2half2_rn(xv.x, xv.y);
            }
        }
        __syncthreads();

        const int wid = tid >> 5, lane = tid & 31;
        const int m0 = (wid >> 1) * 48, n0 = (wid & 1) * 32;
        const int arow = lane & 15, acolb = (lane >> 4) * 8, brow = lane & 15;

        float acc[3][4][4] = {};
        #pragma unroll
        for (int ks = 0; ks < 4; ++ks) {
            uint32_t Af[3][4], Bf[4][2];
            #pragma unroll
            for (int i = 0; i < 3; ++i)
                ldm_x4(Af[i], WHs + (uint32_t)(((m0 + 16 * i + arow) * WS1
                                                + ks * 16 + acolb) * 2));
            #pragma unroll
            for (int t = 0; t < 4; ++t)
                ldm_x2t(Bf[t], XHs + (uint32_t)(((ks * 16 + brow) * WS1
                                                 + n0 + 8 * t) * 2));
            #pragma unroll
            for (int i = 0; i < 3; ++i)
                #pragma unroll
                for (int t = 0; t < 4; ++t)
                    mma_f16(acc[i][t], Af[i], Bf[t]);
        }
        __syncthreads();

        // stage D as fp16 in the sW region
        {
            const int r = lane >> 2, q = lane & 3;
            #pragma unroll
            for (int i = 0; i < 3; ++i)
                #pragma unroll
                for (int t = 0; t < 4; ++t) {
                    int row = m0 + 16 * i + r;
                    int col = n0 + 8 * t + 2 * q;
                    *(half2*)((char*)sm + (row * WS1 + col) * 2) =
                        __floats2half2_rn(acc[i][t][0], acc[i][t][1]);
                    *(half2*)((char*)sm + ((row + 8) * WS1 + col) * 2) =
                        __floats2half2_rn(acc[i][t][2], acc[i][t][3]);
                }
        }
        __syncthreads();

        // copy out to Ybuf: row = c*75 + k*25 + w (c=o/3, k=o%3), L2-direct.
        #pragma unroll
        for (int i = 0; i < 24; ++i) {
            int idx = tid + i * 256;
            int row = idx >> 5;
            int u   = idx & 31;
            uint32_t val = *(uint32_t*)((char*)sm + row * (WS1 * 2) + u * 4);
            int cch = row / 3;
            int kk  = row - 3 * cch;
            size_t yrow = (size_t)(cch * 75 + kk * VV + w);
            __stcg((unsigned int*)((char*)ybuf + (yrow * NTC + jloc) * 2 + u * 4),
                   val);
        }

        __threadfence();
        __syncthreads();
        if (tid == 0) atomicAdd(&g_s1[ch], 1);

    } else {
        // ================= STAGE 2 =================
        if (tid == 0)
            while (((volatile int*)g_s1)[ch] < S1B) __nanosleep(64);
        __syncthreads();
        __threadfence();

        __half* sAh = (__half*)sm;                        // 32 x 88
        __half* sAl = (__half*)(sm + 32 * AST * 2);
        __half* sY  = (__half*)(sm + 64 * AST * 2);       // 80 x 136
        const uint32_t AH = sb;
        const uint32_t AL = sb + 32 * AST * 2;
        const uint32_t YS = sb + 64 * AST * 2;

        const int q    = lb - S1B;
        const int jloc = (q & 15) * JT;
        const int c0   = (q >> 4) * 8;
        const int jg   = jbase + jloc;
        const int n    = jg >> 10;
        const int tt0  = jg & 1023;

        for (int i = tid; i < 80 * 32; i += 256) {
            int r = i >> 5, v = i & 31;
            float a = (r < 75 && v < 25) ? Ag[r * 25 + v] : 0.0f;
            __half h = __float2half_rn(a);
            sAh[v * AST + r] = h;
            sAl[v * AST + r] = __float2half_rn(a - __half2float(h));
        }

        const int wid  = tid >> 5, lane = tid & 31;
        const int jw   = wid * 16;
        const int arow = lane & 15, acolb = (lane >> 4) * 8;
        const int brow = lane & 15;
        const int r4   = lane >> 2, q2 = (lane & 3) * 2;

        int lr[5], lch[5];
        #pragma unroll
        for (int s = 0; s < 5; ++s) {
            int i = tid + s * 256;
            lr[s]  = i >> 4;
            lch[s] = i & 15;
        }

        uint4 pf[5];
        {
            const char* yb = (const char*)ybuf + ((size_t)c0 * 75 * NTC + jloc) * 2;
            #pragma unroll
            for (int s = 0; s < 5; ++s)
                pf[s] = (lr[s] < 75)
                    ? __ldcg((const uint4*)(yb + (size_t)lr[s] * NTC * 2
                                            + lch[s] * 16))
                    : make_uint4(0u, 0u, 0u, 0u);
        }
        __syncthreads();
        #pragma unroll
        for (int s = 0; s < 5; ++s)
            *(uint4*)((char*)sY + (lr[s] * YST + lch[s] * 8) * 2) = pf[s];
        __syncthreads();

        for (int ci = 0; ci < 8; ++ci) {
            const int c = c0 + ci;

            if (ci < 7) {
                const char* yb = (const char*)ybuf
                               + ((size_t)(c + 1) * 75 * NTC + jloc) * 2;
                #pragma unroll
                for (int s = 0; s < 5; ++s)
                    pf[s] = (lr[s] < 75)
                        ? __ldcg((const uint4*)(yb + (size_t)lr[s] * NTC * 2
                                                + lch[s] * 16))
                        : make_uint4(0u, 0u, 0u, 0u);
            }

            float acc[2][2][4] = {};
            #pragma unroll
            for (int ks = 0; ks < 5; ++ks) {
                uint32_t ah0[4], ah1[4], al0[4], al1[4], b0[2], b1[2];
                uint32_t ao0 = (uint32_t)(((arow) * AST + ks * 16 + acolb) * 2);
                uint32_t ao1 = (uint32_t)(((16 + arow) * AST + ks * 16 + acolb) * 2);
                ldm_x4(ah0, AH + ao0);
                ldm_x4(ah1, AH + ao1);
                ldm_x4(al0, AL + ao0);
                ldm_x4(al1, AL + ao1);
                uint32_t boff = (uint32_t)(((ks * 16 + brow) * YST + jw) * 2);
                ldm_x2t(b0, YS + boff);
                ldm_x2t(b1, YS + boff + 16);

                mma_f16(acc[0][0], ah0, b0);  mma_f16(acc[0][0], al0, b0);
                mma_f16(acc[0][1], ah0, b1);  mma_f16(acc[0][1], al0, b1);
                mma_f16(acc[1][0], ah1, b0);  mma_f16(acc[1][0], al1, b0);
                mma_f16(acc[1][1], ah1, b1);  mma_f16(acc[1][1], al1, b1);
            }

            float* ob = out + (((size_t)n * CC + c) * VV) * TT + tt0;
            #pragma unroll
            for (int m = 0; m < 2; ++m)
                #pragma unroll
                for (int t = 0; t < 2; ++t) {
                    int v0 = m * 16 + r4;
                    int jc = jw + t * 8 + q2;
                    if (v0 < VV)
                        *(float2*)(ob + (size_t)v0 * TT + jc) =
                            make_float2(acc[m][t][0], acc[m][t][1]);
                    int v1 = v0 + 8;
                    if (v1 < VV)
                        *(float2*)(ob + (size_t)v1 * TT + jc) =
                            make_float2(acc[m][t][2], acc[m][t][3]);
                }

            if (ci < 7) {
                __syncthreads();
                #pragma unroll
                for (int s = 0; s < 5; ++s)
                    *(uint4*)((char*)sY + (lr[s] * YST + lch[s] * 8) * 2) = pf[s];
                __syncthreads();
            }
        }

        __syncthreads();
        if (tid == 0) atomicAdd(&g_s2[ch], 1);
    }
}

// ---------------------------------------------------------------------------
extern "C" void kernel_launch(void* const* d_in, const int* in_sizes, int n_in,
                              void* d_out, int out_size)
{
    const float* x  = (const float*)d_in[0];
    const float* Wg = (const float*)d_in[1];
    const float* Ag = (const float*)d_in[2];
    float* out = (float*)d_out;

    reset_counters<<<1, 32>>>();

    // dyn smem = max(stage1 36864, stage2 33024) = 36864 (< 48 KB default cap)
    fused_pipe<<<NCHUNK * BLK, 256, 36864>>>(x, Wg, Ag, out);
}

// round 13
// speedup vs baseline: 1.4877x; 1.4262x over previous
#include <cuda_runtime.h>
#include <cuda_fp16.h>
#include <cstdint>
#include <cstddef>

// Shapes: x[32,64,25,1024], W[25,192,64], A[3,25,25], out[32,64,25,1024]
// Stage 1 (HMMA fp16): Yh[c*75 + k*25 + w][j] = sum_c' W[w,c*3+k,c'] x[n,c',w,t]
//   v2: 128-j per CTA as two 64-j halves; W converted once; X half double-buffered.
// Stage 2 (HMMA fp16, A hi/lo): out[n,c,v,t] = sum_r A[v,r] * Yh[c*75+r][j]

#define NB 32
#define CC 64
#define VV 25
#define TT 1024
#define KK 3
#define OO 192
#define NT 32768
#define WS1 72            /* padded row stride (halves) */

// 315 MB fp16 scratch for Y.
__device__ unsigned short g_Yh[(size_t)VV * OO * NT];

// smem layout for stage1 (dynamic, 73728 B)
#define S1_W   0
#define S1_X0  27648
#define S1_X1  36864
#define S1_S   46080
#define S1_TOT 73728

// ---------------------------------------------------------------------------
__device__ __forceinline__ uint32_t smem_u32(const void* p) {
    uint32_t a;
    asm("{ .reg .u64 t; cvta.to.shared.u64 t, %1; cvt.u32.u64 %0, t; }"
        : "=r"(a) : "l"(p));
    return a;
}
__device__ __forceinline__ void ldm_x4(uint32_t a[4], uint32_t addr) {
    asm volatile("ldmatrix.sync.aligned.m8n8.x4.shared.b16 {%0,%1,%2,%3}, [%4];"
        : "=r"(a[0]), "=r"(a[1]), "=r"(a[2]), "=r"(a[3]) : "r"(addr));
}
__device__ __forceinline__ void ldm_x2t(uint32_t b[2], uint32_t addr) {
    asm volatile("ldmatrix.sync.aligned.m8n8.x2.trans.shared.b16 {%0,%1}, [%2];"
        : "=r"(b[0]), "=r"(b[1]) : "r"(addr));
}
__device__ __forceinline__ void mma_f16(float c[4], const uint32_t a[4],
                                        const uint32_t b[2]) {
    asm volatile("mma.sync.aligned.m16n8k16.row.col.f32.f16.f16.f32 "
        "{%0,%1,%2,%3}, {%4,%5,%6,%7}, {%8,%9}, {%0,%1,%2,%3};"
        : "+f"(c[0]), "+f"(c[1]), "+f"(c[2]), "+f"(c[3])
        : "r"(a[0]), "r"(a[1]), "r"(a[2]), "r"(a[3]), "r"(b[0]), "r"(b[1]));
}

// ---------------------------------------------------------------------------
// Stage 1 v2
// ---------------------------------------------------------------------------
__global__ __launch_bounds__(256, 2) void stage1_mma(
    const float* __restrict__ x, const float* __restrict__ Wg)
{
    extern __shared__ char sm[];
    const uint32_t sb = smem_u32(sm);

    const int tid = threadIdx.x;
    const int w   = blockIdx.y;
    const int j0  = blockIdx.x * 128;
    const int n   = j0 >> 10;           // 128 | 1024: never crosses n
    const int t0  = j0 & 1023;

    // ---- W[w] 192x64 fp32 -> fp16 (once per 128 j) ----
    {
        const float* wg = Wg + (size_t)w * OO * 64;
        #pragma unroll
        for (int i = 0; i < 24; ++i) {
            int idx = tid + i * 256;
            int o = idx >> 5, cp = idx & 31;
            float2 wv = *(const float2*)(wg + (size_t)o * 64 + cp * 2);
            *(__half2*)(sm + S1_W + (o * WS1 + cp * 2) * 2) =
                __floats2half2_rn(wv.x, wv.y);
        }
    }
    const float* xb = x + (size_t)n * CC * VV * TT + (size_t)w * TT + t0;
    // ---- X half 0 ----
    {
        #pragma unroll
        for (int i = 0; i < 8; ++i) {
            int idx = tid + i * 256;
            int r = idx >> 5, cp = idx & 31;
            float2 xv = *(const float2*)(xb + (size_t)r * (VV * TT) + cp * 2);
            *(__half2*)(sm + S1_X0 + (r * WS1 + cp * 2) * 2) =
                __floats2half2_rn(xv.x, xv.y);
        }
    }
    __syncthreads();

    const int wid = tid >> 5, lane = tid & 31;
    const int m0 = (wid >> 1) * 48, n0 = (wid & 1) * 32;
    const int arow = lane & 15, acolb = (lane >> 4) * 8, brow = lane & 15;
    const int r4 = lane >> 2, q4 = lane & 3;

    #pragma unroll
    for (int h = 0; h < 2; ++h) {
        const uint32_t XB = sb + (h == 0 ? S1_X0 : S1_X1);

        // prefetch the other half during h=0's MMA
        float2 xr[8];
        if (h == 0) {
            #pragma unroll
            for (int i = 0; i < 8; ++i) {
                int idx = tid + i * 256;
                int r = idx >> 5, cp = idx & 31;
                xr[i] = *(const float2*)(xb + 64 + (size_t)r * (VV * TT) + cp * 2);
            }
        }

        float acc[3][4][4] = {};
        #pragma unroll
        for (int ks = 0; ks < 4; ++ks) {
            uint32_t Af[3][4], Bf[4][2];
            #pragma unroll
            for (int i = 0; i < 3; ++i)
                ldm_x4(Af[i], sb + S1_W + (uint32_t)(((m0 + 16 * i + arow) * WS1
                                                      + ks * 16 + acolb) * 2));
            #pragma unroll
            for (int t = 0; t < 4; ++t)
                ldm_x2t(Bf[t], XB + (uint32_t)(((ks * 16 + brow) * WS1
                                                + n0 + 8 * t) * 2));
            #pragma unroll
            for (int i = 0; i < 3; ++i)
                #pragma unroll
                for (int t = 0; t < 4; ++t)
                    mma_f16(acc[i][t], Af[i], Bf[t]);
        }

        // stage D fragments -> sS (fp16, stride WS1: conflict-free)
        #pragma unroll
        for (int i = 0; i < 3; ++i)
            #pragma unroll
            for (int t = 0; t < 4; ++t) {
                int row = m0 + 16 * i + r4;
                int col = n0 + 8 * t + 2 * q4;
                *(half2*)(sm + S1_S + (row * WS1 + col) * 2) =
                    __floats2half2_rn(acc[i][t][0], acc[i][t][1]);
                *(half2*)(sm + S1_S + ((row + 8) * WS1 + col) * 2) =
                    __floats2half2_rn(acc[i][t][2], acc[i][t][3]);
            }

        // store prefetched X half 1
        if (h == 0) {
            #pragma unroll
            for (int i = 0; i < 8; ++i) {
                int idx = tid + i * 256;
                int r = idx >> 5, cp = idx & 31;
                *(__half2*)(sm + S1_X1 + (r * WS1 + cp * 2) * 2) =
                    __floats2half2_rn(xr[i].x, xr[i].y);
            }
        }
        __syncthreads();      // staging complete (and X1 visible for next h)

        // coalesced copy: 192 rows x 64 halves -> Y at col j0 + h*64
        #pragma unroll
        for (int i = 0; i < 24; ++i) {
            int idx = tid + i * 256;
            int row = idx >> 5;
            int u   = idx & 31;
            uint32_t val = *(uint32_t*)(sm + S1_S + row * (WS1 * 2) + u * 4);
            int cch = row / 3;
            int kk  = row - 3 * cch;
            size_t yrow = (size_t)(cch * 75 + kk * VV + w);
            *(uint32_t*)((char*)g_Yh + (yrow * NT + j0 + h * 64) * 2 + u * 4) = val;
        }
        __syncthreads();      // copy done before next half re-stages sS
    }
}

// ---------------------------------------------------------------------------
// Stage 2 (unchanged from R8): out[v,(c,j)] = sum_r A[v,r] * Yh[c*75+r][j]
// ---------------------------------------------------------------------------
#define JT  128
#define AST 88
#define YST 136

__global__ __launch_bounds__(256) void stage2_mma(
    const float* __restrict__ Ag, float* __restrict__ out)
{
    __shared__ __align__(16) __half sAh[32 * AST];
    __shared__ __align__(16) __half sAl[32 * AST];
    __shared__ __align__(16) __half sY[80 * YST];

    const uint32_t AH = smem_u32(sAh);
    const uint32_t AL = smem_u32(sAl);
    const uint32_t YS = smem_u32(sY);

    const int tid = threadIdx.x;
    const int j0  = blockIdx.x * JT;
    const int c0  = blockIdx.y * 8;
    const int n   = j0 >> 10;
    const int tt0 = j0 & 1023;

    for (int i = tid; i < 80 * 32; i += 256) {
        int r = i >> 5;
        int v = i & 31;
        float a = (r < 75 && v < 25) ? Ag[r * 25 + v] : 0.0f;
        __half h = __float2half_rn(a);
        sAh[v * AST + r] = h;
        sAl[v * AST + r] = __float2half_rn(a - __half2float(h));
    }

    const int wid  = tid >> 5, lane = tid & 31;
    const int jw   = wid * 16;
    const int arow = lane & 15, acolb = (lane >> 4) * 8;
    const int brow = lane & 15;
    const int r4   = lane >> 2, q2 = (lane & 3) * 2;

    int lr[5], lch[5];
    #pragma unroll
    for (int s = 0; s < 5; ++s) {
        int i = tid + s * 256;
        lr[s]  = i >> 4;
        lch[s] = i & 15;
    }

    uint4 pf[5];
    {
        const char* yb = (const char*)g_Yh + ((size_t)c0 * 75 * NT + j0) * 2;
        #pragma unroll
        for (int s = 0; s < 5; ++s)
            pf[s] = (lr[s] < 75)
                ? *(const uint4*)(yb + (size_t)lr[s] * NT * 2 + lch[s] * 16)
                : make_uint4(0u, 0u, 0u, 0u);
    }
    __syncthreads();
    #pragma unroll
    for (int s = 0; s < 5; ++s)
        *(uint4*)((char*)sY + (lr[s] * YST + lch[s] * 8) * 2) = pf[s];
    __syncthreads();

    for (int ci = 0; ci < 8; ++ci) {
        const int c = c0 + ci;

        if (ci < 7) {
            const char* yb = (const char*)g_Yh
                           + ((size_t)(c + 1) * 75 * NT + j0) * 2;
            #pragma unroll
            for (int s = 0; s < 5; ++s)
                pf[s] = (lr[s] < 75)
                    ? *(const uint4*)(yb + (size_t)lr[s] * NT * 2 + lch[s] * 16)
                    : make_uint4(0u, 0u, 0u, 0u);
        }

        float acc[2][2][4] = {};
        #pragma unroll
        for (int ks = 0; ks < 5; ++ks) {
            uint32_t ah0[4], ah1[4], al0[4], al1[4], b0[2], b1[2];
            uint32_t ao0 = (uint32_t)(((arow) * AST + ks * 16 + acolb) * 2);
            uint32_t ao1 = (uint32_t)(((16 + arow) * AST + ks * 16 + acolb) * 2);
            ldm_x4(ah0, AH + ao0);
            ldm_x4(ah1, AH + ao1);
            ldm_x4(al0, AL + ao0);
            ldm_x4(al1, AL + ao1);
            uint32_t boff = (uint32_t)(((ks * 16 + brow) * YST + jw) * 2);
            ldm_x2t(b0, YS + boff);
            ldm_x2t(b1, YS + boff + 16);

            mma_f16(acc[0][0], ah0, b0);  mma_f16(acc[0][0], al0, b0);
            mma_f16(acc[0][1], ah0, b1);  mma_f16(acc[0][1], al0, b1);
            mma_f16(acc[1][0], ah1, b0);  mma_f16(acc[1][0], al1, b0);
            mma_f16(acc[1][1], ah1, b1);  mma_f16(acc[1][1], al1, b1);
        }

        float* ob = out + (((size_t)n * CC + c) * VV) * TT + tt0;
        #pragma unroll
        for (int m = 0; m < 2; ++m)
            #pragma unroll
            for (int t = 0; t < 2; ++t) {
                int v0 = m * 16 + r4;
                int jc = jw + t * 8 + q2;
                if (v0 < VV)
                    *(float2*)(ob + (size_t)v0 * TT + jc) =
                        make_float2(acc[m][t][0], acc[m][t][1]);
                int v1 = v0 + 8;
                if (v1 < VV)
                    *(float2*)(ob + (size_t)v1 * TT + jc) =
                        make_float2(acc[m][t][2], acc[m][t][3]);
            }

        if (ci < 7) {
            __syncthreads();
            #pragma unroll
            for (int s = 0; s < 5; ++s)
                *(uint4*)((char*)sY + (lr[s] * YST + lch[s] * 8) * 2) = pf[s];
            __syncthreads();
        }
    }
}

// ---------------------------------------------------------------------------
extern "C" void kernel_launch(void* const* d_in, const int* in_sizes, int n_in,
                              void* d_out, int out_size)
{
    const float* x  = (const float*)d_in[0];
    const float* Wg = (const float*)d_in[1];
    const float* Ag = (const float*)d_in[2];
    float* out = (float*)d_out;

    cudaFuncSetAttribute(stage1_mma,
                         cudaFuncAttributeMaxDynamicSharedMemorySize,
                         S1_TOT);

    dim3 g1(NT / 128, VV);            // (256, 25)
    stage1_mma<<<g1, 256, S1_TOT>>>(x, Wg);

    dim3 g2(NT / JT, 8);              // (256, 8)
    stage2_mma<<<g2, 256>>>(Ag, out);
}

// round 14
// speedup vs baseline: 1.5342x; 1.0313x over previous
#include <cuda_runtime.h>
#include <cuda_fp16.h>
#include <cstdint>
#include <cstddef>

// Shapes: x[32,64,25,1024], W[25,192,64], A[3,25,25], out[32,64,25,1024]
// Stage 1 (HMMA fp16): Yh[c*75 + k*25 + w][j] = sum_c' W[w,c*3+k,c'] x[n,c',w,t]
//   (R13 version: 128-j per CTA, W converted once, X halves double-buffered)
// Stage 2 (HMMA fp16, single-pass A): out[n,c,v,t] = sum_r A[v,r]*Yh[c*75+r][j]
//   v2: sY double-buffered (1 sync/phase), x4t B-frags, half the MMA work.

#define NB 32
#define CC 64
#define VV 25
#define TT 1024
#define KK 3
#define OO 192
#define NT 32768
#define WS1 72            /* stage1 padded row stride (halves) */

// 315 MB fp16 scratch for Y.
__device__ unsigned short g_Yh[(size_t)VV * OO * NT];

// stage1 smem layout (dynamic, 73728 B)
#define S1_W   0
#define S1_X0  27648
#define S1_X1  36864
#define S1_S   46080
#define S1_TOT 73728

// stage2 smem layout (dynamic, 49152 B)
#define AST    88
#define YST    136
#define YBUF   (80 * YST * 2)     /* 21760 */
#define S2_A   0
#define S2_Y0  5632
#define S2_TOT (5632 + 2 * YBUF)  /* 49152 */

// ---------------------------------------------------------------------------
__device__ __forceinline__ uint32_t smem_u32(const void* p) {
    uint32_t a;
    asm("{ .reg .u64 t; cvta.to.shared.u64 t, %1; cvt.u32.u64 %0, t; }"
        : "=r"(a) : "l"(p));
    return a;
}
__device__ __forceinline__ void ldm_x4(uint32_t a[4], uint32_t addr) {
    asm volatile("ldmatrix.sync.aligned.m8n8.x4.shared.b16 {%0,%1,%2,%3}, [%4];"
        : "=r"(a[0]), "=r"(a[1]), "=r"(a[2]), "=r"(a[3]) : "r"(addr));
}
__device__ __forceinline__ void ldm_x2t(uint32_t b[2], uint32_t addr) {
    asm volatile("ldmatrix.sync.aligned.m8n8.x2.trans.shared.b16 {%0,%1}, [%2];"
        : "=r"(b[0]), "=r"(b[1]) : "r"(addr));
}
__device__ __forceinline__ void ldm_x4t(uint32_t a[4], uint32_t addr) {
    asm volatile("ldmatrix.sync.aligned.m8n8.x4.trans.shared.b16 {%0,%1,%2,%3}, [%4];"
        : "=r"(a[0]), "=r"(a[1]), "=r"(a[2]), "=r"(a[3]) : "r"(addr));
}
__device__ __forceinline__ void mma_f16(float c[4], const uint32_t a[4],
                                        const uint32_t b[2]) {
    asm volatile("mma.sync.aligned.m16n8k16.row.col.f32.f16.f16.f32 "
        "{%0,%1,%2,%3}, {%4,%5,%6,%7}, {%8,%9}, {%0,%1,%2,%3};"
        : "+f"(c[0]), "+f"(c[1]), "+f"(c[2]), "+f"(c[3])
        : "r"(a[0]), "r"(a[1]), "r"(a[2]), "r"(a[3]), "r"(b[0]), "r"(b[1]));
}

// ---------------------------------------------------------------------------
// Stage 1 (unchanged from R13)
// ---------------------------------------------------------------------------
__global__ __launch_bounds__(256, 2) void stage1_mma(
    const float* __restrict__ x, const float* __restrict__ Wg)
{
    extern __shared__ char sm[];
    const uint32_t sb = smem_u32(sm);

    const int tid = threadIdx.x;
    const int w   = blockIdx.y;
    const int j0  = blockIdx.x * 128;
    const int n   = j0 >> 10;
    const int t0  = j0 & 1023;

    {
        const float* wg = Wg + (size_t)w * OO * 64;
        #pragma unroll
        for (int i = 0; i < 24; ++i) {
            int idx = tid + i * 256;
            int o = idx >> 5, cp = idx & 31;
            float2 wv = *(const float2*)(wg + (size_t)o * 64 + cp * 2);
            *(__half2*)(sm + S1_W + (o * WS1 + cp * 2) * 2) =
                __floats2half2_rn(wv.x, wv.y);
        }
    }
    const float* xb = x + (size_t)n * CC * VV * TT + (size_t)w * TT + t0;
    {
        #pragma unroll
        for (int i = 0; i < 8; ++i) {
            int idx = tid + i * 256;
            int r = idx >> 5, cp = idx & 31;
            float2 xv = *(const float2*)(xb + (size_t)r * (VV * TT) + cp * 2);
            *(__half2*)(sm + S1_X0 + (r * WS1 + cp * 2) * 2) =
                __floats2half2_rn(xv.x, xv.y);
        }
    }
    __syncthreads();

    const int wid = tid >> 5, lane = tid & 31;
    const int m0 = (wid >> 1) * 48, n0 = (wid & 1) * 32;
    const int arow = lane & 15, acolb = (lane >> 4) * 8, brow = lane & 15;
    const int r4 = lane >> 2, q4 = lane & 3;

    #pragma unroll
    for (int h = 0; h < 2; ++h) {
        const uint32_t XB = sb + (h == 0 ? S1_X0 : S1_X1);

        float2 xr[8];
        if (h == 0) {
            #pragma unroll
            for (int i = 0; i < 8; ++i) {
                int idx = tid + i * 256;
                int r = idx >> 5, cp = idx & 31;
                xr[i] = *(const float2*)(xb + 64 + (size_t)r * (VV * TT) + cp * 2);
            }
        }

        float acc[3][4][4] = {};
        #pragma unroll
        for (int ks = 0; ks < 4; ++ks) {
            uint32_t Af[3][4], Bf[4][2];
            #pragma unroll
            for (int i = 0; i < 3; ++i)
                ldm_x4(Af[i], sb + S1_W + (uint32_t)(((m0 + 16 * i + arow) * WS1
                                                      + ks * 16 + acolb) * 2));
            #pragma unroll
            for (int t = 0; t < 4; ++t)
                ldm_x2t(Bf[t], XB + (uint32_t)(((ks * 16 + brow) * WS1
                                                + n0 + 8 * t) * 2));
            #pragma unroll
            for (int i = 0; i < 3; ++i)
                #pragma unroll
                for (int t = 0; t < 4; ++t)
                    mma_f16(acc[i][t], Af[i], Bf[t]);
        }

        #pragma unroll
        for (int i = 0; i < 3; ++i)
            #pragma unroll
            for (int t = 0; t < 4; ++t) {
                int row = m0 + 16 * i + r4;
                int col = n0 + 8 * t + 2 * q4;
                *(half2*)(sm + S1_S + (row * WS1 + col) * 2) =
                    __floats2half2_rn(acc[i][t][0], acc[i][t][1]);
                *(half2*)(sm + S1_S + ((row + 8) * WS1 + col) * 2) =
                    __floats2half2_rn(acc[i][t][2], acc[i][t][3]);
            }

        if (h == 0) {
            #pragma unroll
            for (int i = 0; i < 8; ++i) {
                int idx = tid + i * 256;
                int r = idx >> 5, cp = idx & 31;
                *(__half2*)(sm + S1_X1 + (r * WS1 + cp * 2) * 2) =
                    __floats2half2_rn(xr[i].x, xr[i].y);
            }
        }
        __syncthreads();

        #pragma unroll
        for (int i = 0; i < 24; ++i) {
            int idx = tid + i * 256;
            int row = idx >> 5;
            int u   = idx & 31;
            uint32_t val = *(uint32_t*)(sm + S1_S + row * (WS1 * 2) + u * 4);
            int cch = row / 3;
            int kk  = row - 3 * cch;
            size_t yrow = (size_t)(cch * 75 + kk * VV + w);
            *(uint32_t*)((char*)g_Yh + (yrow * NT + j0 + h * 64) * 2 + u * 4) = val;
        }
        __syncthreads();
    }
}

// ---------------------------------------------------------------------------
// Stage 2 v2: single-pass fp16 A, double-buffered sY, 1 sync per c-phase.
// ---------------------------------------------------------------------------
#define JT 128

__global__ __launch_bounds__(256) void stage2_mma(
    const float* __restrict__ Ag, float* __restrict__ out)
{
    extern __shared__ char sm[];
    const uint32_t sb = smem_u32(sm);
    __half* sA = (__half*)(sm + S2_A);

    const int tid = threadIdx.x;
    const int j0  = blockIdx.x * JT;
    const int c0  = blockIdx.y * 8;
    const int n   = j0 >> 10;
    const int tt0 = j0 & 1023;

    // Graph A fp16 single pass (zero-padded v>=25, r>=75).
    for (int i = tid; i < 80 * 32; i += 256) {
        int r = i >> 5, v = i & 31;
        float a = (r < 75 && v < 25) ? Ag[r * 25 + v] : 0.0f;
        sA[v * AST + r] = __float2half_rn(a);
    }

    const int wid  = tid >> 5, lane = tid & 31;
    const int jw   = wid * 16;
    const int arow = lane & 15, acolb = (lane >> 4) * 8;
    const int brow = lane & 15, bcol = (lane >> 4) * 8;
    const int r4   = lane >> 2, q2 = (lane & 3) * 2;

    int lr[5], lch[5];
    #pragma unroll
    for (int s = 0; s < 5; ++s) {
        int i = tid + s * 256;
        lr[s]  = i >> 4;
        lch[s] = i & 15;
    }

    // prefetch c0 and store into buffer 0 (no sync needed: disjoint regions)
    uint4 pf[5];
    {
        const char* yb = (const char*)g_Yh + ((size_t)c0 * 75 * NT + j0) * 2;
        #pragma unroll
        for (int s = 0; s < 5; ++s)
            pf[s] = (lr[s] < 75)
                ? *(const uint4*)(yb + (size_t)lr[s] * NT * 2 + lch[s] * 16)
                : make_uint4(0u, 0u, 0u, 0u);
    }
    #pragma unroll
    for (int s = 0; s < 5; ++s)
        *(uint4*)(sm + S2_Y0 + (lr[s] * YST + lch[s] * 8) * 2) = pf[s];

    for (int ci = 0; ci < 8; ++ci) {
        const int c = c0 + ci;
        const uint32_t YB = sb + S2_Y0 + (uint32_t)((ci & 1) * YBUF);

        __syncthreads();   // buf(ci) stored by all; prior buf reads done; A ready

        // issue next phase's loads (complete during MMA below)
        if (ci < 7) {
            const char* yb = (const char*)g_Yh
                           + ((size_t)(c + 1) * 75 * NT + j0) * 2;
            #pragma unroll
            for (int s = 0; s < 5; ++s)
                pf[s] = (lr[s] < 75)
                    ? *(const uint4*)(yb + (size_t)lr[s] * NT * 2 + lch[s] * 16)
                    : make_uint4(0u, 0u, 0u, 0u);
        }

        float acc[2][2][4] = {};
        #pragma unroll
        for (int ks = 0; ks < 5; ++ks) {
            uint32_t a0[4], a1[4], Bf[4];
            ldm_x4(a0, sb + S2_A + (uint32_t)(((arow) * AST
                                               + ks * 16 + acolb) * 2));
            ldm_x4(a1, sb + S2_A + (uint32_t)(((16 + arow) * AST
                                               + ks * 16 + acolb) * 2));
            ldm_x4t(Bf, YB + (uint32_t)(((ks * 16 + brow) * YST
                                         + jw + bcol) * 2));
            mma_f16(acc[0][0], a0, Bf);
            mma_f16(acc[0][1], a0, Bf + 2);
            mma_f16(acc[1][0], a1, Bf);
            mma_f16(acc[1][1], a1, Bf + 2);
        }

        float* ob = out + (((size_t)n * CC + c) * VV) * TT + tt0;
        #pragma unroll
        for (int m = 0; m < 2; ++m)
            #pragma unroll
            for (int t = 0; t < 2; ++t) {
                int v0 = m * 16 + r4;
                int jc = jw + t * 8 + q2;
                if (v0 < VV)
                    *(float2*)(ob + (size_t)v0 * TT + jc) =
                        make_float2(acc[m][t][0], acc[m][t][1]);
                int v1 = v0 + 8;
                if (v1 < VV)
                    *(float2*)(ob + (size_t)v1 * TT + jc) =
                        make_float2(acc[m][t][2], acc[m][t][3]);
            }

        // store next phase into the other buffer (nobody reads it this phase)
        if (ci < 7) {
            char* yd = sm + S2_Y0 + ((ci & 1) ^ 1) * YBUF;
            #pragma unroll
            for (int s = 0; s < 5; ++s)
                *(uint4*)(yd + (lr[s] * YST + lch[s] * 8) * 2) = pf[s];
        }
    }
}

// ---------------------------------------------------------------------------
extern "C" void kernel_launch(void* const* d_in, const int* in_sizes, int n_in,
                              void* d_out, int out_size)
{
    const float* x  = (const float*)d_in[0];
    const float* Wg = (const float*)d_in[1];
    const float* Ag = (const float*)d_in[2];
    float* out = (float*)d_out;

    cudaFuncSetAttribute(stage1_mma,
                         cudaFuncAttributeMaxDynamicSharedMemorySize, S1_TOT);
    cudaFuncSetAttribute(stage2_mma,
                         cudaFuncAttributeMaxDynamicSharedMemorySize, S2_TOT);

    dim3 g1(NT / 128, VV);            // (256, 25)
    stage1_mma<<<g1, 256, S1_TOT>>>(x, Wg);

    dim3 g2(NT / JT, 8);              // (256, 8)
    stage2_mma<<<g2, 256, S2_TOT>>>(Ag, out);
}